// round 5
// baseline (speedup 1.0000x reference)
#include <cuda_runtime.h>
#include <cstdint>

#define SEQ 2048
#define EMB 2048
#define NB 2
#define NH 16
#define HD 128
#define MTOT (NB*SEQ)
#define FST 132   // flash smem row stride (128 + 4 pad)

// Scratch (allocation-free rule: __device__ globals)
__device__ float g_q[(size_t)MTOT * EMB];
__device__ float g_k[(size_t)MTOT * EMB];
__device__ float g_v[(size_t)MTOT * EMB];
__device__ float g_o[(size_t)MTOT * EMB];
__device__ float g_x[(size_t)MTOT * EMB];     // tf32-rounded X
__device__ float g_wq[(size_t)EMB * EMB];     // tf32-rounded weights
__device__ float g_wk[(size_t)EMB * EMB];
__device__ float g_wv[(size_t)EMB * EMB];
__device__ float g_wo[(size_t)EMB * EMB];
__device__ float g_cos[SEQ * (HD/2)];
__device__ float g_sin[SEQ * (HD/2)];

__device__ __forceinline__ uint32_t f2tf(float x){
  uint32_t y; asm("cvt.rna.tf32.f32 %0, %1;" : "=r"(y) : "f"(x)); return y;
}
__device__ __forceinline__ float f2tff(float x){ return __uint_as_float(f2tf(x)); }

__device__ __forceinline__ uint32_t smem_u32(const void* p){
  uint32_t a;
  asm("{ .reg .u64 t; cvta.to.shared.u64 t, %1; cvt.u32.u64 %0, t; }" : "=r"(a) : "l"(p));
  return a;
}

__device__ __forceinline__ void cp16(uint32_t dst, const void* src){
  asm volatile("cp.async.cg.shared.global [%0], [%1], 16;" :: "r"(dst), "l"(src));
}
#define CP_COMMIT() asm volatile("cp.async.commit_group;" ::: "memory")
#define CP_WAIT1()  asm volatile("cp.async.wait_group 1;" ::: "memory")

__device__ __forceinline__ void mma8(float* d, const uint32_t* a, const uint32_t* b){
  asm volatile("mma.sync.aligned.m16n8k8.row.col.f32.tf32.tf32.f32 "
    "{%0,%1,%2,%3},{%4,%5,%6,%7},{%8,%9},{%0,%1,%2,%3};\n"
    : "+f"(d[0]), "+f"(d[1]), "+f"(d[2]), "+f"(d[3])
    : "r"(a[0]), "r"(a[1]), "r"(a[2]), "r"(a[3]), "r"(b[0]), "r"(b[1]));
}

// ---------------------------------------------------------------------------
// TF32 pre-rounding pass (float4 streaming)
// ---------------------------------------------------------------------------
__global__ void round_tf32_kernel(const float* __restrict__ src, float* __restrict__ dst, int n4){
  int i = blockIdx.x*blockDim.x + threadIdx.x;
  if (i >= n4) return;
  float4 v = ((const float4*)src)[i];
  v.x=f2tff(v.x); v.y=f2tff(v.y); v.z=f2tff(v.z); v.w=f2tff(v.w);
  ((float4*)dst)[i] = v;
}

// ---------------------------------------------------------------------------
// GEMM: C[M,N] = A[M,K] @ W[N,K]^T + bias[N]. Inputs pre-rounded to tf32.
// BM=BN=128, BK=32. 128 threads = 4 warps, each warp a 64x64 tile.
// cp.async 2-stage; 2 CTAs/SM. mode 0/1/2: A=g_x, W=g_wq/k/v, C=g_q/k/v.
// mode 3: A=g_o, W=g_wo, C=Out.
// ---------------------------------------------------------------------------
#define GST 36
#define TILE_F (128*GST)
#define G_SMEM (4*TILE_F*4)   // bytes: As[2] + Bs[2]

__global__ __launch_bounds__(128,2) void gemm_bias_kernel(
    const float* __restrict__ bias, float* __restrict__ Outp, int mode)
{
  extern __shared__ float sm4[];
  float* As = sm4;               // 2 stages
  float* Bs = sm4 + 2*TILE_F;    // 2 stages

  const float* A = (mode == 3) ? g_o : g_x;
  const float* W = (mode==0) ? g_wq : (mode==1) ? g_wk : (mode==2) ? g_wv : g_wo;
  float* C = (mode==0) ? g_q : (mode==1) ? g_k : (mode==2) ? g_v : Outp;

  const int tid = threadIdx.x;
  const int bn = blockIdx.x, bm = blockIdx.y;
  const int lane = tid & 31, w = tid >> 5;
  const int wm = (w >> 1) << 6;   // 0,64
  const int wn = (w & 1) << 6;    // 0,64
  const int g = lane >> 2, t4 = lane & 3;

  const float* Ag = A + (size_t)(bm*128 + tid) * EMB;
  const float* Wg = W + (size_t)(bn*128 + tid) * EMB;
  const uint32_t sAs = smem_u32(As) + tid*GST*4;
  const uint32_t sBs = smem_u32(Bs) + tid*GST*4;

  float acc[4][8][4];
  #pragma unroll
  for (int mt=0;mt<4;mt++)
    #pragma unroll
    for (int nt=0;nt<8;nt++)
      #pragma unroll
      for (int e=0;e<4;e++) acc[mt][nt][e] = 0.f;

  // prologue: stage 0
  #pragma unroll
  for (int cg = 0; cg < 8; cg++){
    cp16(sAs + cg*16, Ag + cg*4);
    cp16(sBs + cg*16, Wg + cg*4);
  }
  CP_COMMIT();

  for (int kt = 0; kt < 64; kt++){
    const int buf = kt & 1;
    if (kt < 63){
      const int nb = (kt+1) & 1;
      #pragma unroll
      for (int cg = 0; cg < 8; cg++){
        cp16(sAs + (nb*TILE_F)*4 + cg*16, Ag + (kt+1)*32 + cg*4);
        cp16(sBs + (nb*TILE_F)*4 + cg*16, Wg + (kt+1)*32 + cg*4);
      }
    }
    CP_COMMIT();
    CP_WAIT1();
    __syncthreads();

    const float* a = As + buf*TILE_F;
    const float* bsm = Bs + buf*TILE_F;
    #pragma unroll
    for (int ks = 0; ks < 4; ks++){
      const int k = ks*8;
      uint32_t af[4][4], bf[8][2];
      #pragma unroll
      for (int mt=0; mt<4; mt++){
        int r = wm + mt*16 + g;
        af[mt][0] = __float_as_uint(a[r*GST + k + t4]);
        af[mt][1] = __float_as_uint(a[(r+8)*GST + k + t4]);
        af[mt][2] = __float_as_uint(a[r*GST + k + t4 + 4]);
        af[mt][3] = __float_as_uint(a[(r+8)*GST + k + t4 + 4]);
      }
      #pragma unroll
      for (int nt=0; nt<8; nt++){
        int n = wn + nt*8 + g;
        bf[nt][0] = __float_as_uint(bsm[n*GST + k + t4]);
        bf[nt][1] = __float_as_uint(bsm[n*GST + k + t4 + 4]);
      }
      #pragma unroll
      for (int mt=0; mt<4; mt++)
        #pragma unroll
        for (int nt=0; nt<8; nt++)
          mma8(acc[mt][nt], af[mt], bf[nt]);
    }
    __syncthreads();
  }

  #pragma unroll
  for (int mt=0; mt<4; mt++){
    int row = bm*128 + wm + mt*16 + g;
    #pragma unroll
    for (int nt=0; nt<8; nt++){
      int col = bn*128 + wn + nt*8 + 2*t4;
      float b0 = bias[col], b1 = bias[col+1];
      float2 v0 = make_float2(acc[mt][nt][0]+b0, acc[mt][nt][1]+b1);
      float2 v1 = make_float2(acc[mt][nt][2]+b0, acc[mt][nt][3]+b1);
      *(float2*)&C[(size_t)row*EMB + col] = v0;
      *(float2*)&C[(size_t)(row+8)*EMB + col] = v1;
    }
  }
}

// ---------------------------------------------------------------------------
// RoPE tables + apply
// ---------------------------------------------------------------------------
__global__ void rope_tables_kernel(){
  int idx = blockIdx.x*blockDim.x + threadIdx.x;
  if (idx >= SEQ*(HD/2)) return;
  int s = idx >> 6;
  int j = idx & 63;
  double inv = pow(10000.0, -(double)j/64.0);
  float ang = (float)s * (float)inv;
  g_cos[idx] = (float)cos((double)ang);
  g_sin[idx] = (float)sin((double)ang);
}

__global__ void rope_apply_kernel(){
  int idx = blockIdx.x*blockDim.x + threadIdx.x;
  int j = idx & 63;
  int h = (idx >> 6) & 15;
  int m = idx >> 10;
  int s = m & (SEQ-1);
  size_t base = (size_t)m*EMB + h*HD;
  float c = g_cos[s*64 + j], sn = g_sin[s*64 + j];
  float q1 = g_q[base + j], q2 = g_q[base + j + 64];
  g_q[base + j]      = q1*c - q2*sn;
  g_q[base + j + 64] = q1*sn + q2*c;
  float k1 = g_k[base + j], k2 = g_k[base + j + 64];
  g_k[base + j]      = k1*c - k2*sn;
  g_k[base + j + 64] = k1*sn + k2*c;
}

// ---------------------------------------------------------------------------
// Flash attention, causal. (epilogue now writes tf32-rounded O for the
// final projection's A operand)
// ---------------------------------------------------------------------------
#define FLASH_SMEM_FLOATS (3*128*FST + 256 + 256 + 128)

__global__ __launch_bounds__(256,1) void flash_kernel(const unsigned char* __restrict__ amask){
  extern __shared__ float sm[];
  float* Qs   = sm;
  float* Ks   = sm + 128*FST;
  float* Vs   = sm + 2*128*FST;
  float* redm = sm + 3*128*FST;
  float* reds = redm + 256;
  float* km   = reds + 256;

  const int tid = threadIdx.x;
  const int bh = blockIdx.x;
  const int qt = blockIdx.y;
  const int b = bh >> 4, h = bh & 15;
  const int lane = tid & 31, w = tid >> 5;
  const int wm = (w >> 1) << 5;
  const int wnn = (w & 1);
  const int wn = wnn << 6;
  const int g = lane >> 2, t4 = lane & 3;

  const size_t headoff = (size_t)h * HD;
  const float* Qg = g_q + ((size_t)(b*SEQ + qt*128)) * EMB + headoff;
  const int lr = tid >> 5;
  const int lc = (tid & 31) << 2;

  #pragma unroll
  for (int i = 0; i < 16; i++){
    int r = lr + i*8;
    float4 v = *(const float4*)(Qg + (size_t)r*EMB + lc);
    v.x=f2tff(v.x); v.y=f2tff(v.y); v.z=f2tff(v.z); v.w=f2tff(v.w);
    *(float4*)&Qs[r*FST + lc] = v;
  }

  float o_acc[2][8][4];
  #pragma unroll
  for (int mt=0;mt<2;mt++)
    #pragma unroll
    for (int nt=0;nt<8;nt++)
      #pragma unroll
      for (int e=0;e<4;e++) o_acc[mt][nt][e] = 0.f;
  float m_prev[4], l_run[4];
  #pragma unroll
  for (int ri=0;ri<4;ri++){ m_prev[ri] = -1e30f; l_run[ri] = 0.f; }

  const float scale = 0.088388347648318447f;

  for (int kt = 0; kt <= qt; kt++){
    __syncthreads();
    const float* Kg = g_k + ((size_t)(b*SEQ + kt*128)) * EMB + headoff;
    const float* Vg = g_v + ((size_t)(b*SEQ + kt*128)) * EMB + headoff;
    #pragma unroll
    for (int i = 0; i < 16; i++){
      int r = lr + i*8;
      float4 v = *(const float4*)(Kg + (size_t)r*EMB + lc);
      v.x=f2tff(v.x); v.y=f2tff(v.y); v.z=f2tff(v.z); v.w=f2tff(v.w);
      *(float4*)&Ks[r*FST + lc] = v;
      float4 u = *(const float4*)(Vg + (size_t)r*EMB + lc);
      u.x=f2tff(u.x); u.y=f2tff(u.y); u.z=f2tff(u.z); u.w=f2tff(u.w);
      *(float4*)&Vs[r*FST + lc] = u;
    }
    if (tid < 128) km[tid] = amask[b*SEQ + kt*128 + tid] ? -1e30f : 0.f;
    __syncthreads();

    float s_acc[2][8][4];
    #pragma unroll
    for (int mt=0;mt<2;mt++)
      #pragma unroll
      for (int nt=0;nt<8;nt++)
        #pragma unroll
        for (int e=0;e<4;e++) s_acc[mt][nt][e] = 0.f;

    #pragma unroll
    for (int ks=0; ks<16; ks++){
      const int k = ks*8;
      uint32_t af[2][4], bf[8][2];
      #pragma unroll
      for (int mt=0;mt<2;mt++){
        int r = wm + mt*16 + g;
        af[mt][0] = __float_as_uint(Qs[r*FST + k + t4]);
        af[mt][1] = __float_as_uint(Qs[(r+8)*FST + k + t4]);
        af[mt][2] = __float_as_uint(Qs[r*FST + k + t4 + 4]);
        af[mt][3] = __float_as_uint(Qs[(r+8)*FST + k + t4 + 4]);
      }
      #pragma unroll
      for (int nt=0;nt<8;nt++){
        int n = wn + nt*8 + g;
        bf[nt][0] = __float_as_uint(Ks[n*FST + k + t4]);
        bf[nt][1] = __float_as_uint(Ks[n*FST + k + t4 + 4]);
      }
      #pragma unroll
      for (int mt=0;mt<2;mt++)
        #pragma unroll
        for (int nt=0;nt<8;nt++)
          mma8(s_acc[mt][nt], af[mt], bf[nt]);
    }

    const bool diag = (kt == qt);
    #pragma unroll
    for (int mt=0;mt<2;mt++)
      #pragma unroll
      for (int nt=0;nt<8;nt++)
        #pragma unroll
        for (int e=0;e<4;e++){
          int colL = wn + nt*8 + 2*t4 + (e & 1);
          int rowL = wm + mt*16 + g + ((e >> 1) << 3);
          float v = s_acc[mt][nt][e]*scale + km[colL];
          if (diag && colL > rowL) v = -1e30f;
          s_acc[mt][nt][e] = v;
        }

    #pragma unroll
    for (int ri=0;ri<4;ri++){
      int mt = ri>>1, hh = ri&1;
      float mx = -1e30f;
      #pragma unroll
      for (int nt=0;nt<8;nt++)
        mx = fmaxf(mx, fmaxf(s_acc[mt][nt][hh*2], s_acc[mt][nt][hh*2+1]));
      mx = fmaxf(mx, __shfl_xor_sync(0xffffffffu, mx, 1));
      mx = fmaxf(mx, __shfl_xor_sync(0xffffffffu, mx, 2));
      if (t4 == 0) redm[wnn*128 + wm + mt*16 + g + hh*8] = mx;
    }
    __syncthreads();

    float m_new[4], alpha[4], rsum[4];
    #pragma unroll
    for (int ri=0;ri<4;ri++){
      int rl = wm + (ri>>1)*16 + g + (ri&1)*8;
      float mtile = fmaxf(redm[rl], redm[128+rl]);
      m_new[ri] = fmaxf(m_prev[ri], mtile);
      alpha[ri] = __expf(m_prev[ri] - m_new[ri]);
      rsum[ri] = 0.f;
    }

    #pragma unroll
    for (int mt=0;mt<2;mt++)
      #pragma unroll
      for (int nt=0;nt<8;nt++)
        #pragma unroll
        for (int hh=0;hh<2;hh++){
          int ri = mt*2 + hh;
          float p0 = __expf(s_acc[mt][nt][hh*2]   - m_new[ri]);
          float p1 = __expf(s_acc[mt][nt][hh*2+1] - m_new[ri]);
          rsum[ri] += p0 + p1;
          int rowL = wm + mt*16 + g + hh*8;
          int colL = wn + nt*8 + 2*t4;
          float2 pv; pv.x = f2tff(p0); pv.y = f2tff(p1);
          *(float2*)&Ks[rowL*FST + colL] = pv;
          o_acc[mt][nt][hh*2]   *= alpha[ri];
          o_acc[mt][nt][hh*2+1] *= alpha[ri];
        }

    #pragma unroll
    for (int ri=0;ri<4;ri++){
      float s0 = rsum[ri];
      s0 += __shfl_xor_sync(0xffffffffu, s0, 1);
      s0 += __shfl_xor_sync(0xffffffffu, s0, 2);
      if (t4 == 0) reds[wnn*128 + wm + (ri>>1)*16 + g + (ri&1)*8] = s0;
    }
    __syncthreads();
    #pragma unroll
    for (int ri=0;ri<4;ri++){
      int rl = wm + (ri>>1)*16 + g + (ri&1)*8;
      l_run[ri] = l_run[ri]*alpha[ri] + reds[rl] + reds[128+rl];
      m_prev[ri] = m_new[ri];
    }

    #pragma unroll
    for (int ks=0; ks<16; ks++){
      const int k = ks*8;
      uint32_t af[2][4], bf[8][2];
      #pragma unroll
      for (int mt=0;mt<2;mt++){
        int r = wm + mt*16 + g;
        af[mt][0] = __float_as_uint(Ks[r*FST + k + t4]);
        af[mt][1] = __float_as_uint(Ks[(r+8)*FST + k + t4]);
        af[mt][2] = __float_as_uint(Ks[r*FST + k + t4 + 4]);
        af[mt][3] = __float_as_uint(Ks[(r+8)*FST + k + t4 + 4]);
      }
      #pragma unroll
      for (int nt=0;nt<8;nt++){
        int n = wn + nt*8 + g;
        bf[nt][0] = __float_as_uint(Vs[(k + t4)*FST + n]);
        bf[nt][1] = __float_as_uint(Vs[(k + t4 + 4)*FST + n]);
      }
      #pragma unroll
      for (int mt=0;mt<2;mt++)
        #pragma unroll
        for (int nt=0;nt<8;nt++)
          mma8(o_acc[mt][nt], af[mt], bf[nt]);
    }
  }

  // write O rounded to tf32 (A-operand of the final projection)
  float* Og = g_o + ((size_t)(b*SEQ + qt*128)) * EMB + headoff;
  #pragma unroll
  for (int mt=0;mt<2;mt++)
    #pragma unroll
    for (int hh=0;hh<2;hh++){
      int ri = mt*2 + hh;
      float inv = 1.0f / l_run[ri];
      int rowL = wm + mt*16 + g + hh*8;
      #pragma unroll
      for (int nt=0;nt<8;nt++){
        int colL = wn + nt*8 + 2*t4;
        float2 ov;
        ov.x = f2tff(o_acc[mt][nt][hh*2]   * inv);
        ov.y = f2tff(o_acc[mt][nt][hh*2+1] * inv);
        *(float2*)&Og[(size_t)rowL*EMB + colL] = ov;
      }
    }
}

// ---------------------------------------------------------------------------
extern "C" void kernel_launch(void* const* d_in, const int* in_sizes, int n_in,
                              void* d_out, int out_size){
  (void)in_sizes; (void)n_in; (void)out_size;
  const float* x  = (const float*)d_in[0];
  const float* wq = (const float*)d_in[1];
  const float* bq = (const float*)d_in[2];
  const float* wk = (const float*)d_in[3];
  const float* bk = (const float*)d_in[4];
  const float* wv = (const float*)d_in[5];
  const float* bv = (const float*)d_in[6];
  const float* wo = (const float*)d_in[7];
  const float* bo = (const float*)d_in[8];
  const unsigned char* amask = (const unsigned char*)d_in[10];
  float* out = (float*)d_out;

  cudaFuncSetAttribute(flash_kernel, cudaFuncAttributeMaxDynamicSharedMemorySize,
                       FLASH_SMEM_FLOATS * (int)sizeof(float));
  cudaFuncSetAttribute(gemm_bias_kernel, cudaFuncAttributeMaxDynamicSharedMemorySize,
                       G_SMEM);

  // resolve __device__ scratch addresses (host API, not an allocation)
  float *p_x, *p_wq, *p_wk, *p_wv, *p_wo;
  cudaGetSymbolAddress((void**)&p_x,  g_x);
  cudaGetSymbolAddress((void**)&p_wq, g_wq);
  cudaGetSymbolAddress((void**)&p_wk, g_wk);
  cudaGetSymbolAddress((void**)&p_wv, g_wv);
  cudaGetSymbolAddress((void**)&p_wo, g_wo);

  rope_tables_kernel<<<(SEQ*64 + 255)/256, 256>>>();

  const int nX4 = MTOT*EMB/4, nW4 = EMB*EMB/4;
  round_tf32_kernel<<<(nX4+255)/256, 256>>>(x,  p_x,  nX4);
  round_tf32_kernel<<<(nW4+255)/256, 256>>>(wq, p_wq, nW4);
  round_tf32_kernel<<<(nW4+255)/256, 256>>>(wk, p_wk, nW4);
  round_tf32_kernel<<<(nW4+255)/256, 256>>>(wv, p_wv, nW4);
  round_tf32_kernel<<<(nW4+255)/256, 256>>>(wo, p_wo, nW4);

  dim3 ggrid(EMB/128, MTOT/128);
  gemm_bias_kernel<<<ggrid, 128, G_SMEM>>>(bq, nullptr, 0);
  gemm_bias_kernel<<<ggrid, 128, G_SMEM>>>(bk, nullptr, 1);
  gemm_bias_kernel<<<ggrid, 128, G_SMEM>>>(bv, nullptr, 2);

  rope_apply_kernel<<<(MTOT*NH*64 + 255)/256, 256>>>();

  flash_kernel<<<dim3(NB*NH, SEQ/128), 256, FLASH_SMEM_FLOATS*(int)sizeof(float)>>>(amask);

  gemm_bias_kernel<<<ggrid, 128, G_SMEM>>>(bo, out, 3);
}

// round 6
// speedup vs baseline: 1.4801x; 1.4801x over previous
#include <cuda_runtime.h>
#include <cstdint>

#define SEQ 2048
#define EMB 2048
#define NB 2
#define NH 16
#define HD 128
#define MTOT (NB*SEQ)
#define FST 132   // flash smem row stride (128 + 4 pad)

// Scratch (allocation-free rule: __device__ globals)
__device__ float g_q[(size_t)MTOT * EMB];
__device__ float g_k[(size_t)MTOT * EMB];
__device__ float g_v[(size_t)MTOT * EMB];
__device__ float g_o[(size_t)MTOT * EMB];     // flash writes tf32-rounded O
__device__ float g_x[(size_t)MTOT * EMB];     // tf32-rounded X
__device__ float g_wq[(size_t)EMB * EMB];     // tf32-rounded weights
__device__ float g_wk[(size_t)EMB * EMB];
__device__ float g_wv[(size_t)EMB * EMB];
__device__ float g_wo[(size_t)EMB * EMB];
__device__ float g_cos[SEQ * (HD/2)];
__device__ float g_sin[SEQ * (HD/2)];

__device__ __forceinline__ uint32_t f2tf(float x){
  uint32_t y; asm("cvt.rna.tf32.f32 %0, %1;" : "=r"(y) : "f"(x)); return y;
}
__device__ __forceinline__ float f2tff(float x){ return __uint_as_float(f2tf(x)); }

__device__ __forceinline__ uint32_t smem_u32(const void* p){
  uint32_t a;
  asm("{ .reg .u64 t; cvta.to.shared.u64 t, %1; cvt.u32.u64 %0, t; }" : "=r"(a) : "l"(p));
  return a;
}

__device__ __forceinline__ void cp16(uint32_t dst, const void* src){
  asm volatile("cp.async.cg.shared.global [%0], [%1], 16;" :: "r"(dst), "l"(src));
}
#define CP_COMMIT() asm volatile("cp.async.commit_group;" ::: "memory")
#define CP_WAIT1()  asm volatile("cp.async.wait_group 1;" ::: "memory")

__device__ __forceinline__ void mma8(float* d, const uint32_t* a, const uint32_t* b){
  asm volatile("mma.sync.aligned.m16n8k8.row.col.f32.tf32.tf32.f32 "
    "{%0,%1,%2,%3},{%4,%5,%6,%7},{%8,%9},{%0,%1,%2,%3};\n"
    : "+f"(d[0]), "+f"(d[1]), "+f"(d[2]), "+f"(d[3])
    : "r"(a[0]), "r"(a[1]), "r"(a[2]), "r"(a[3]), "r"(b[0]), "r"(b[1]));
}

// ---------------------------------------------------------------------------
// TF32 pre-rounding pass (float4 streaming)
// ---------------------------------------------------------------------------
__global__ void round_tf32_kernel(const float* __restrict__ src, float* __restrict__ dst, int n4){
  int i = blockIdx.x*blockDim.x + threadIdx.x;
  if (i >= n4) return;
  float4 v = ((const float4*)src)[i];
  v.x=f2tff(v.x); v.y=f2tff(v.y); v.z=f2tff(v.z); v.w=f2tff(v.w);
  ((float4*)dst)[i] = v;
}

// ---------------------------------------------------------------------------
// GEMM (R3 proven config): C[M,N] = A[M,K] @ W[N,K]^T + bias[N]
// BM=BN=128, BK=32, 256 threads (8 warps 4x2), TF32 m16n8k8.
// cp.async double-buffered; inputs pre-rounded to tf32 (no cvt in mainloop).
// mode 0/1/2: A=g_x, W=g_wq/k/v, C=g_q/k/v.  mode 3: A=g_o, W=g_wo, C=Out.
// ---------------------------------------------------------------------------
#define GST 36                 // smem row stride (floats)
#define TILE_F (128*GST)       // floats per (A or B) stage

__global__ __launch_bounds__(256,2) void gemm_bias_kernel(
    const float* __restrict__ bias, float* __restrict__ Outp, int mode)
{
  __shared__ float As[2*TILE_F];
  __shared__ float Bs[2*TILE_F];
  const float* A = (mode == 3) ? g_o : g_x;
  const float* W = (mode==0) ? g_wq : (mode==1) ? g_wk : (mode==2) ? g_wv : g_wo;
  float* C = (mode==0) ? g_q : (mode==1) ? g_k : (mode==2) ? g_v : Outp;

  const int tid = threadIdx.x;
  const int bn = blockIdx.x, bm = blockIdx.y;
  const int lane = tid & 31, w = tid >> 5;
  const int wm = (w >> 1) << 5;   // 0,32,64,96
  const int wn = (w & 1) << 6;    // 0,64
  const int g = lane >> 2, t4 = lane & 3;

  const int prow = tid >> 3;          // 0..31 (4 passes of 32 rows)
  const int pf4  = (tid & 7) << 2;    // float col 0..28
  const float* Ag = A + (size_t)(bm*128 + prow) * EMB + pf4;
  const float* Wg = W + (size_t)(bn*128 + prow) * EMB + pf4;
  const uint32_t sAs = smem_u32(As) + (prow*GST + pf4)*4;
  const uint32_t sBs = smem_u32(Bs) + (prow*GST + pf4)*4;

  float acc[2][8][4];
  #pragma unroll
  for (int mt=0;mt<2;mt++)
    #pragma unroll
    for (int nt=0;nt<8;nt++)
      #pragma unroll
      for (int e=0;e<4;e++) acc[mt][nt][e] = 0.f;

  // prologue: stage 0
  #pragma unroll
  for (int i = 0; i < 4; i++){
    cp16(sAs + i*32*GST*4, Ag + (size_t)i*32*EMB);
    cp16(sBs + i*32*GST*4, Wg + (size_t)i*32*EMB);
  }
  CP_COMMIT();

  for (int kt = 0; kt < 64; kt++){
    const int buf = kt & 1;
    if (kt < 63){
      const int nb = (kt+1) & 1;
      #pragma unroll
      for (int i = 0; i < 4; i++){
        cp16(sAs + (nb*TILE_F + i*32*GST)*4, Ag + (kt+1)*32 + (size_t)i*32*EMB);
        cp16(sBs + (nb*TILE_F + i*32*GST)*4, Wg + (kt+1)*32 + (size_t)i*32*EMB);
      }
    }
    CP_COMMIT();
    CP_WAIT1();
    __syncthreads();

    const float* a = As + buf*TILE_F;
    const float* bsm = Bs + buf*TILE_F;
    #pragma unroll
    for (int ks = 0; ks < 4; ks++){
      const int k = ks*8;
      uint32_t af[2][4], bf[8][2];
      #pragma unroll
      for (int mt=0; mt<2; mt++){
        int r = wm + mt*16 + g;
        af[mt][0] = __float_as_uint(a[r*GST + k + t4]);
        af[mt][1] = __float_as_uint(a[(r+8)*GST + k + t4]);
        af[mt][2] = __float_as_uint(a[r*GST + k + t4 + 4]);
        af[mt][3] = __float_as_uint(a[(r+8)*GST + k + t4 + 4]);
      }
      #pragma unroll
      for (int nt=0; nt<8; nt++){
        int n = wn + nt*8 + g;
        bf[nt][0] = __float_as_uint(bsm[n*GST + k + t4]);
        bf[nt][1] = __float_as_uint(bsm[n*GST + k + t4 + 4]);
      }
      #pragma unroll
      for (int mt=0; mt<2; mt++)
        #pragma unroll
        for (int nt=0; nt<8; nt++)
          mma8(acc[mt][nt], af[mt], bf[nt]);
    }
    __syncthreads();
  }

  #pragma unroll
  for (int mt=0; mt<2; mt++){
    int row = bm*128 + wm + mt*16 + g;
    #pragma unroll
    for (int nt=0; nt<8; nt++){
      int col = bn*128 + wn + nt*8 + 2*t4;
      float b0 = bias[col], b1 = bias[col+1];
      float2 v0 = make_float2(acc[mt][nt][0]+b0, acc[mt][nt][1]+b1);
      float2 v1 = make_float2(acc[mt][nt][2]+b0, acc[mt][nt][3]+b1);
      *(float2*)&C[(size_t)row*EMB + col] = v0;
      *(float2*)&C[(size_t)(row+8)*EMB + col] = v1;
    }
  }
}

// ---------------------------------------------------------------------------
// RoPE tables + apply
// ---------------------------------------------------------------------------
__global__ void rope_tables_kernel(){
  int idx = blockIdx.x*blockDim.x + threadIdx.x;
  if (idx >= SEQ*(HD/2)) return;
  int s = idx >> 6;
  int j = idx & 63;
  double inv = pow(10000.0, -(double)j/64.0);
  float ang = (float)s * (float)inv;
  g_cos[idx] = (float)cos((double)ang);
  g_sin[idx] = (float)sin((double)ang);
}

__global__ void rope_apply_kernel(){
  int idx = blockIdx.x*blockDim.x + threadIdx.x;
  int j = idx & 63;
  int h = (idx >> 6) & 15;
  int m = idx >> 10;
  int s = m & (SEQ-1);
  size_t base = (size_t)m*EMB + h*HD;
  float c = g_cos[s*64 + j], sn = g_sin[s*64 + j];
  float q1 = g_q[base + j], q2 = g_q[base + j + 64];
  g_q[base + j]      = q1*c - q2*sn;
  g_q[base + j + 64] = q1*sn + q2*c;
  float k1 = g_k[base + j], k2 = g_k[base + j + 64];
  g_k[base + j]      = k1*c - k2*sn;
  g_k[base + j + 64] = k1*sn + k2*c;
}

// ---------------------------------------------------------------------------
// Flash attention, causal (R1-proven). O written tf32-rounded for final gemm.
// ---------------------------------------------------------------------------
#define FLASH_SMEM_FLOATS (3*128*FST + 256 + 256 + 128)

__global__ __launch_bounds__(256,1) void flash_kernel(const unsigned char* __restrict__ amask){
  extern __shared__ float sm[];
  float* Qs   = sm;
  float* Ks   = sm + 128*FST;
  float* Vs   = sm + 2*128*FST;
  float* redm = sm + 3*128*FST;
  float* reds = redm + 256;
  float* km   = reds + 256;

  const int tid = threadIdx.x;
  const int bh = blockIdx.x;
  const int qt = blockIdx.y;
  const int b = bh >> 4, h = bh & 15;
  const int lane = tid & 31, w = tid >> 5;
  const int wm = (w >> 1) << 5;
  const int wnn = (w & 1);
  const int wn = wnn << 6;
  const int g = lane >> 2, t4 = lane & 3;

  const size_t headoff = (size_t)h * HD;
  const float* Qg = g_q + ((size_t)(b*SEQ + qt*128)) * EMB + headoff;
  const int lr = tid >> 5;
  const int lc = (tid & 31) << 2;

  #pragma unroll
  for (int i = 0; i < 16; i++){
    int r = lr + i*8;
    float4 v = *(const float4*)(Qg + (size_t)r*EMB + lc);
    v.x=f2tff(v.x); v.y=f2tff(v.y); v.z=f2tff(v.z); v.w=f2tff(v.w);
    *(float4*)&Qs[r*FST + lc] = v;
  }

  float o_acc[2][8][4];
  #pragma unroll
  for (int mt=0;mt<2;mt++)
    #pragma unroll
    for (int nt=0;nt<8;nt++)
      #pragma unroll
      for (int e=0;e<4;e++) o_acc[mt][nt][e] = 0.f;
  float m_prev[4], l_run[4];
  #pragma unroll
  for (int ri=0;ri<4;ri++){ m_prev[ri] = -1e30f; l_run[ri] = 0.f; }

  const float scale = 0.088388347648318447f;

  for (int kt = 0; kt <= qt; kt++){
    __syncthreads();
    const float* Kg = g_k + ((size_t)(b*SEQ + kt*128)) * EMB + headoff;
    const float* Vg = g_v + ((size_t)(b*SEQ + kt*128)) * EMB + headoff;
    #pragma unroll
    for (int i = 0; i < 16; i++){
      int r = lr + i*8;
      float4 v = *(const float4*)(Kg + (size_t)r*EMB + lc);
      v.x=f2tff(v.x); v.y=f2tff(v.y); v.z=f2tff(v.z); v.w=f2tff(v.w);
      *(float4*)&Ks[r*FST + lc] = v;
      float4 u = *(const float4*)(Vg + (size_t)r*EMB + lc);
      u.x=f2tff(u.x); u.y=f2tff(u.y); u.z=f2tff(u.z); u.w=f2tff(u.w);
      *(float4*)&Vs[r*FST + lc] = u;
    }
    if (tid < 128) km[tid] = amask[b*SEQ + kt*128 + tid] ? -1e30f : 0.f;
    __syncthreads();

    float s_acc[2][8][4];
    #pragma unroll
    for (int mt=0;mt<2;mt++)
      #pragma unroll
      for (int nt=0;nt<8;nt++)
        #pragma unroll
        for (int e=0;e<4;e++) s_acc[mt][nt][e] = 0.f;

    #pragma unroll
    for (int ks=0; ks<16; ks++){
      const int k = ks*8;
      uint32_t af[2][4], bf[8][2];
      #pragma unroll
      for (int mt=0;mt<2;mt++){
        int r = wm + mt*16 + g;
        af[mt][0] = __float_as_uint(Qs[r*FST + k + t4]);
        af[mt][1] = __float_as_uint(Qs[(r+8)*FST + k + t4]);
        af[mt][2] = __float_as_uint(Qs[r*FST + k + t4 + 4]);
        af[mt][3] = __float_as_uint(Qs[(r+8)*FST + k + t4 + 4]);
      }
      #pragma unroll
      for (int nt=0;nt<8;nt++){
        int n = wn + nt*8 + g;
        bf[nt][0] = __float_as_uint(Ks[n*FST + k + t4]);
        bf[nt][1] = __float_as_uint(Ks[n*FST + k + t4 + 4]);
      }
      #pragma unroll
      for (int mt=0;mt<2;mt++)
        #pragma unroll
        for (int nt=0;nt<8;nt++)
          mma8(s_acc[mt][nt], af[mt], bf[nt]);
    }

    const bool diag = (kt == qt);
    #pragma unroll
    for (int mt=0;mt<2;mt++)
      #pragma unroll
      for (int nt=0;nt<8;nt++)
        #pragma unroll
        for (int e=0;e<4;e++){
          int colL = wn + nt*8 + 2*t4 + (e & 1);
          int rowL = wm + mt*16 + g + ((e >> 1) << 3);
          float v = s_acc[mt][nt][e]*scale + km[colL];
          if (diag && colL > rowL) v = -1e30f;
          s_acc[mt][nt][e] = v;
        }

    #pragma unroll
    for (int ri=0;ri<4;ri++){
      int mt = ri>>1, hh = ri&1;
      float mx = -1e30f;
      #pragma unroll
      for (int nt=0;nt<8;nt++)
        mx = fmaxf(mx, fmaxf(s_acc[mt][nt][hh*2], s_acc[mt][nt][hh*2+1]));
      mx = fmaxf(mx, __shfl_xor_sync(0xffffffffu, mx, 1));
      mx = fmaxf(mx, __shfl_xor_sync(0xffffffffu, mx, 2));
      if (t4 == 0) redm[wnn*128 + wm + mt*16 + g + hh*8] = mx;
    }
    __syncthreads();

    float m_new[4], alpha[4], rsum[4];
    #pragma unroll
    for (int ri=0;ri<4;ri++){
      int rl = wm + (ri>>1)*16 + g + (ri&1)*8;
      float mtile = fmaxf(redm[rl], redm[128+rl]);
      m_new[ri] = fmaxf(m_prev[ri], mtile);
      alpha[ri] = __expf(m_prev[ri] - m_new[ri]);
      rsum[ri] = 0.f;
    }

    #pragma unroll
    for (int mt=0;mt<2;mt++)
      #pragma unroll
      for (int nt=0;nt<8;nt++)
        #pragma unroll
        for (int hh=0;hh<2;hh++){
          int ri = mt*2 + hh;
          float p0 = __expf(s_acc[mt][nt][hh*2]   - m_new[ri]);
          float p1 = __expf(s_acc[mt][nt][hh*2+1] - m_new[ri]);
          rsum[ri] += p0 + p1;
          int rowL = wm + mt*16 + g + hh*8;
          int colL = wn + nt*8 + 2*t4;
          float2 pv; pv.x = f2tff(p0); pv.y = f2tff(p1);
          *(float2*)&Ks[rowL*FST + colL] = pv;
          o_acc[mt][nt][hh*2]   *= alpha[ri];
          o_acc[mt][nt][hh*2+1] *= alpha[ri];
        }

    #pragma unroll
    for (int ri=0;ri<4;ri++){
      float s0 = rsum[ri];
      s0 += __shfl_xor_sync(0xffffffffu, s0, 1);
      s0 += __shfl_xor_sync(0xffffffffu, s0, 2);
      if (t4 == 0) reds[wnn*128 + wm + (ri>>1)*16 + g + (ri&1)*8] = s0;
    }
    __syncthreads();
    #pragma unroll
    for (int ri=0;ri<4;ri++){
      int rl = wm + (ri>>1)*16 + g + (ri&1)*8;
      l_run[ri] = l_run[ri]*alpha[ri] + reds[rl] + reds[128+rl];
      m_prev[ri] = m_new[ri];
    }

    #pragma unroll
    for (int ks=0; ks<16; ks++){
      const int k = ks*8;
      uint32_t af[2][4], bf[8][2];
      #pragma unroll
      for (int mt=0;mt<2;mt++){
        int r = wm + mt*16 + g;
        af[mt][0] = __float_as_uint(Ks[r*FST + k + t4]);
        af[mt][1] = __float_as_uint(Ks[(r+8)*FST + k + t4]);
        af[mt][2] = __float_as_uint(Ks[r*FST + k + t4 + 4]);
        af[mt][3] = __float_as_uint(Ks[(r+8)*FST + k + t4 + 4]);
      }
      #pragma unroll
      for (int nt=0;nt<8;nt++){
        int n = wn + nt*8 + g;
        bf[nt][0] = __float_as_uint(Vs[(k + t4)*FST + n]);
        bf[nt][1] = __float_as_uint(Vs[(k + t4 + 4)*FST + n]);
      }
      #pragma unroll
      for (int mt=0;mt<2;mt++)
        #pragma unroll
        for (int nt=0;nt<8;nt++)
          mma8(o_acc[mt][nt], af[mt], bf[nt]);
    }
  }

  // write O rounded to tf32 (A-operand of the final projection)
  float* Og = g_o + ((size_t)(b*SEQ + qt*128)) * EMB + headoff;
  #pragma unroll
  for (int mt=0;mt<2;mt++)
    #pragma unroll
    for (int hh=0;hh<2;hh++){
      int ri = mt*2 + hh;
      float inv = 1.0f / l_run[ri];
      int rowL = wm + mt*16 + g + hh*8;
      #pragma unroll
      for (int nt=0;nt<8;nt++){
        int colL = wn + nt*8 + 2*t4;
        float2 ov;
        ov.x = f2tff(o_acc[mt][nt][hh*2]   * inv);
        ov.y = f2tff(o_acc[mt][nt][hh*2+1] * inv);
        *(float2*)&Og[(size_t)rowL*EMB + colL] = ov;
      }
    }
}

// ---------------------------------------------------------------------------
extern "C" void kernel_launch(void* const* d_in, const int* in_sizes, int n_in,
                              void* d_out, int out_size){
  (void)in_sizes; (void)n_in; (void)out_size;
  const float* x  = (const float*)d_in[0];
  const float* wq = (const float*)d_in[1];
  const float* bq = (const float*)d_in[2];
  const float* wk = (const float*)d_in[3];
  const float* bk = (const float*)d_in[4];
  const float* wv = (const float*)d_in[5];
  const float* bv = (const float*)d_in[6];
  const float* wo = (const float*)d_in[7];
  const float* bo = (const float*)d_in[8];
  const unsigned char* amask = (const unsigned char*)d_in[10];
  float* out = (float*)d_out;

  cudaFuncSetAttribute(flash_kernel, cudaFuncAttributeMaxDynamicSharedMemorySize,
                       FLASH_SMEM_FLOATS * (int)sizeof(float));

  float *p_x, *p_wq, *p_wk, *p_wv, *p_wo;
  cudaGetSymbolAddress((void**)&p_x,  g_x);
  cudaGetSymbolAddress((void**)&p_wq, g_wq);
  cudaGetSymbolAddress((void**)&p_wk, g_wk);
  cudaGetSymbolAddress((void**)&p_wv, g_wv);
  cudaGetSymbolAddress((void**)&p_wo, g_wo);

  rope_tables_kernel<<<(SEQ*64 + 255)/256, 256>>>();

  const int nX4 = MTOT*EMB/4, nW4 = EMB*EMB/4;
  round_tf32_kernel<<<(nX4+255)/256, 256>>>(x,  p_x,  nX4);
  round_tf32_kernel<<<(nW4+255)/256, 256>>>(wq, p_wq, nW4);
  round_tf32_kernel<<<(nW4+255)/256, 256>>>(wk, p_wk, nW4);
  round_tf32_kernel<<<(nW4+255)/256, 256>>>(wv, p_wv, nW4);
  round_tf32_kernel<<<(nW4+255)/256, 256>>>(wo, p_wo, nW4);

  dim3 ggrid(EMB/128, MTOT/128);
  gemm_bias_kernel<<<ggrid, 256>>>(bq, nullptr, 0);
  gemm_bias_kernel<<<ggrid, 256>>>(bk, nullptr, 1);
  gemm_bias_kernel<<<ggrid, 256>>>(bv, nullptr, 2);

  rope_apply_kernel<<<(MTOT*NH*64 + 255)/256, 256>>>();

  flash_kernel<<<dim3(NB*NH, SEQ/128), 256, FLASH_SMEM_FLOATS*(int)sizeof(float)>>>(amask);

  gemm_bias_kernel<<<ggrid, 256>>>(bo, out, 3);
}

// round 7
// speedup vs baseline: 1.5090x; 1.0195x over previous
#include <cuda_runtime.h>
#include <cstdint>

#define SEQ 2048
#define EMB 2048
#define NB 2
#define NH 16
#define HD 128
#define MTOT (NB*SEQ)
#define FST 132   // flash smem row stride (128 + 4 pad); FST*4=528B (16B-aligned)

// Scratch (allocation-free rule: __device__ globals)
__device__ float g_q[(size_t)MTOT * EMB];
__device__ float g_k[(size_t)MTOT * EMB];
__device__ float g_v[(size_t)MTOT * EMB];     // tf32-rounded (gemm mode-2 epilogue)
__device__ float g_o[(size_t)MTOT * EMB];     // flash writes tf32-rounded O
__device__ float g_x[(size_t)MTOT * EMB];     // tf32-rounded X
__device__ float g_wq[(size_t)EMB * EMB];     // tf32-rounded weights
__device__ float g_wk[(size_t)EMB * EMB];
__device__ float g_wv[(size_t)EMB * EMB];
__device__ float g_wo[(size_t)EMB * EMB];
__device__ float g_cos[SEQ * (HD/2)];
__device__ float g_sin[SEQ * (HD/2)];

__device__ __forceinline__ uint32_t f2tf(float x){
  uint32_t y; asm("cvt.rna.tf32.f32 %0, %1;" : "=r"(y) : "f"(x)); return y;
}
__device__ __forceinline__ float f2tff(float x){ return __uint_as_float(f2tf(x)); }

__device__ __forceinline__ uint32_t smem_u32(const void* p){
  uint32_t a;
  asm("{ .reg .u64 t; cvta.to.shared.u64 t, %1; cvt.u32.u64 %0, t; }" : "=r"(a) : "l"(p));
  return a;
}

__device__ __forceinline__ void cp16(uint32_t dst, const void* src){
  asm volatile("cp.async.cg.shared.global [%0], [%1], 16;" :: "r"(dst), "l"(src));
}
#define CP_COMMIT() asm volatile("cp.async.commit_group;" ::: "memory")
#define CP_WAIT1()  asm volatile("cp.async.wait_group 1;" ::: "memory")
#define CP_WAIT0()  asm volatile("cp.async.wait_group 0;" ::: "memory")

__device__ __forceinline__ void mma8(float* d, const uint32_t* a, const uint32_t* b){
  asm volatile("mma.sync.aligned.m16n8k8.row.col.f32.tf32.tf32.f32 "
    "{%0,%1,%2,%3},{%4,%5,%6,%7},{%8,%9},{%0,%1,%2,%3};\n"
    : "+f"(d[0]), "+f"(d[1]), "+f"(d[2]), "+f"(d[3])
    : "r"(a[0]), "r"(a[1]), "r"(a[2]), "r"(a[3]), "r"(b[0]), "r"(b[1]));
}

// ---------------------------------------------------------------------------
// TF32 pre-rounding pass (float4 streaming)
// ---------------------------------------------------------------------------
__global__ void round_tf32_kernel(const float* __restrict__ src, float* __restrict__ dst, int n4){
  int i = blockIdx.x*blockDim.x + threadIdx.x;
  if (i >= n4) return;
  float4 v = ((const float4*)src)[i];
  v.x=f2tff(v.x); v.y=f2tff(v.y); v.z=f2tff(v.z); v.w=f2tff(v.w);
  ((float4*)dst)[i] = v;
}

// ---------------------------------------------------------------------------
// GEMM (proven config): C[M,N] = A[M,K] @ W[N,K]^T + bias[N]
// BM=BN=128, BK=32, 256 threads (8 warps 4x2), TF32 m16n8k8.
// mode 0/1/2: A=g_x, W=g_wq/k/v, C=g_q/k/v (mode 2 writes tf32-rounded).
// mode 3: A=g_o, W=g_wo, C=Out (fp32).
// ---------------------------------------------------------------------------
#define GST 36
#define TILE_F (128*GST)

__global__ __launch_bounds__(256,2) void gemm_bias_kernel(
    const float* __restrict__ bias, float* __restrict__ Outp, int mode)
{
  __shared__ float As[2*TILE_F];
  __shared__ float Bs[2*TILE_F];
  const float* A = (mode == 3) ? g_o : g_x;
  const float* W = (mode==0) ? g_wq : (mode==1) ? g_wk : (mode==2) ? g_wv : g_wo;
  float* C = (mode==0) ? g_q : (mode==1) ? g_k : (mode==2) ? g_v : Outp;
  const bool roundOut = (mode == 2);

  const int tid = threadIdx.x;
  const int bn = blockIdx.x, bm = blockIdx.y;
  const int lane = tid & 31, w = tid >> 5;
  const int wm = (w >> 1) << 5;   // 0,32,64,96
  const int wn = (w & 1) << 6;    // 0,64
  const int g = lane >> 2, t4 = lane & 3;

  const int prow = tid >> 3;
  const int pf4  = (tid & 7) << 2;
  const float* Ag = A + (size_t)(bm*128 + prow) * EMB + pf4;
  const float* Wg = W + (size_t)(bn*128 + prow) * EMB + pf4;
  const uint32_t sAs = smem_u32(As) + (prow*GST + pf4)*4;
  const uint32_t sBs = smem_u32(Bs) + (prow*GST + pf4)*4;

  float acc[2][8][4];
  #pragma unroll
  for (int mt=0;mt<2;mt++)
    #pragma unroll
    for (int nt=0;nt<8;nt++)
      #pragma unroll
      for (int e=0;e<4;e++) acc[mt][nt][e] = 0.f;

  #pragma unroll
  for (int i = 0; i < 4; i++){
    cp16(sAs + i*32*GST*4, Ag + (size_t)i*32*EMB);
    cp16(sBs + i*32*GST*4, Wg + (size_t)i*32*EMB);
  }
  CP_COMMIT();

  for (int kt = 0; kt < 64; kt++){
    const int buf = kt & 1;
    if (kt < 63){
      const int nb = (kt+1) & 1;
      #pragma unroll
      for (int i = 0; i < 4; i++){
        cp16(sAs + (nb*TILE_F + i*32*GST)*4, Ag + (kt+1)*32 + (size_t)i*32*EMB);
        cp16(sBs + (nb*TILE_F + i*32*GST)*4, Wg + (kt+1)*32 + (size_t)i*32*EMB);
      }
    }
    CP_COMMIT();
    CP_WAIT1();
    __syncthreads();

    const float* a = As + buf*TILE_F;
    const float* bsm = Bs + buf*TILE_F;
    #pragma unroll
    for (int ks = 0; ks < 4; ks++){
      const int k = ks*8;
      uint32_t af[2][4], bf[8][2];
      #pragma unroll
      for (int mt=0; mt<2; mt++){
        int r = wm + mt*16 + g;
        af[mt][0] = __float_as_uint(a[r*GST + k + t4]);
        af[mt][1] = __float_as_uint(a[(r+8)*GST + k + t4]);
        af[mt][2] = __float_as_uint(a[r*GST + k + t4 + 4]);
        af[mt][3] = __float_as_uint(a[(r+8)*GST + k + t4 + 4]);
      }
      #pragma unroll
      for (int nt=0; nt<8; nt++){
        int n = wn + nt*8 + g;
        bf[nt][0] = __float_as_uint(bsm[n*GST + k + t4]);
        bf[nt][1] = __float_as_uint(bsm[n*GST + k + t4 + 4]);
      }
      #pragma unroll
      for (int mt=0; mt<2; mt++)
        #pragma unroll
        for (int nt=0; nt<8; nt++)
          mma8(acc[mt][nt], af[mt], bf[nt]);
    }
    __syncthreads();
  }

  #pragma unroll
  for (int mt=0; mt<2; mt++){
    int row = bm*128 + wm + mt*16 + g;
    #pragma unroll
    for (int nt=0; nt<8; nt++){
      int col = bn*128 + wn + nt*8 + 2*t4;
      float b0 = bias[col], b1 = bias[col+1];
      float2 v0 = make_float2(acc[mt][nt][0]+b0, acc[mt][nt][1]+b1);
      float2 v1 = make_float2(acc[mt][nt][2]+b0, acc[mt][nt][3]+b1);
      if (roundOut){
        v0.x=f2tff(v0.x); v0.y=f2tff(v0.y); v1.x=f2tff(v1.x); v1.y=f2tff(v1.y);
      }
      *(float2*)&C[(size_t)row*EMB + col] = v0;
      *(float2*)&C[(size_t)(row+8)*EMB + col] = v1;
    }
  }
}

// ---------------------------------------------------------------------------
// RoPE tables + apply (apply now writes tf32-rounded q,k — same bits flash
// would have produced at load time)
// ---------------------------------------------------------------------------
__global__ void rope_tables_kernel(){
  int idx = blockIdx.x*blockDim.x + threadIdx.x;
  if (idx >= SEQ*(HD/2)) return;
  int s = idx >> 6;
  int j = idx & 63;
  double inv = pow(10000.0, -(double)j/64.0);
  float ang = (float)s * (float)inv;
  g_cos[idx] = (float)cos((double)ang);
  g_sin[idx] = (float)sin((double)ang);
}

__global__ void rope_apply_kernel(){
  int idx = blockIdx.x*blockDim.x + threadIdx.x;
  int j = idx & 63;
  int h = (idx >> 6) & 15;
  int m = idx >> 10;
  int s = m & (SEQ-1);
  size_t base = (size_t)m*EMB + h*HD;
  float c = g_cos[s*64 + j], sn = g_sin[s*64 + j];
  float q1 = g_q[base + j], q2 = g_q[base + j + 64];
  g_q[base + j]      = f2tff(q1*c - q2*sn);
  g_q[base + j + 64] = f2tff(q1*sn + q2*c);
  float k1 = g_k[base + j], k2 = g_k[base + j + 64];
  g_k[base + j]      = f2tff(k1*c - k2*sn);
  g_k[base + j + 64] = f2tff(k1*sn + k2*c);
}

// ---------------------------------------------------------------------------
// Flash attention, causal. Q/K/V pre-rounded -> pure cp.async copies.
// ---------------------------------------------------------------------------
#define FLASH_SMEM_FLOATS (3*128*FST + 256 + 256 + 128)

__global__ __launch_bounds__(256,1) void flash_kernel(const unsigned char* __restrict__ amask){
  extern __shared__ float sm[];
  float* Qs   = sm;
  float* Ks   = sm + 128*FST;
  float* Vs   = sm + 2*128*FST;
  float* redm = sm + 3*128*FST;
  float* reds = redm + 256;
  float* km   = reds + 256;

  const int tid = threadIdx.x;
  const int bh = blockIdx.x;
  const int qt = blockIdx.y;
  const int b = bh >> 4, h = bh & 15;
  const int lane = tid & 31, w = tid >> 5;
  const int wm = (w >> 1) << 5;
  const int wnn = (w & 1);
  const int wn = wnn << 6;
  const int g = lane >> 2, t4 = lane & 3;

  const size_t headoff = (size_t)h * HD;
  const int lr = tid >> 5;          // 0..7
  const int lc = (tid & 31) << 2;   // 0..124

  const float* Qg = g_q + ((size_t)(b*SEQ + qt*128) + lr) * EMB + headoff + lc;
  const uint32_t sQ = smem_u32(Qs) + (lr*FST + lc)*4;
  const uint32_t sK = smem_u32(Ks) + (lr*FST + lc)*4;
  const uint32_t sV = smem_u32(Vs) + (lr*FST + lc)*4;

  #pragma unroll
  for (int i = 0; i < 16; i++)
    cp16(sQ + i*8*FST*4, Qg + (size_t)i*8*EMB);
  CP_COMMIT();

  float o_acc[2][8][4];
  #pragma unroll
  for (int mt=0;mt<2;mt++)
    #pragma unroll
    for (int nt=0;nt<8;nt++)
      #pragma unroll
      for (int e=0;e<4;e++) o_acc[mt][nt][e] = 0.f;
  float m_prev[4], l_run[4];
  #pragma unroll
  for (int ri=0;ri<4;ri++){ m_prev[ri] = -1e30f; l_run[ri] = 0.f; }

  const float scale = 0.088388347648318447f;

  for (int kt = 0; kt <= qt; kt++){
    __syncthreads();   // prior PV mma done before overwriting Ks/Vs
    const float* Kg = g_k + ((size_t)(b*SEQ + kt*128) + lr) * EMB + headoff + lc;
    const float* Vg = g_v + ((size_t)(b*SEQ + kt*128) + lr) * EMB + headoff + lc;
    #pragma unroll
    for (int i = 0; i < 16; i++){
      cp16(sK + i*8*FST*4, Kg + (size_t)i*8*EMB);
      cp16(sV + i*8*FST*4, Vg + (size_t)i*8*EMB);
    }
    CP_COMMIT();
    if (tid < 128) km[tid] = amask[b*SEQ + kt*128 + tid] ? -1e30f : 0.f;
    CP_WAIT0();
    __syncthreads();

    // ---- S = Q K^T ----
    float s_acc[2][8][4];
    #pragma unroll
    for (int mt=0;mt<2;mt++)
      #pragma unroll
      for (int nt=0;nt<8;nt++)
        #pragma unroll
        for (int e=0;e<4;e++) s_acc[mt][nt][e] = 0.f;

    #pragma unroll
    for (int ks=0; ks<16; ks++){
      const int k = ks*8;
      uint32_t af[2][4], bf[8][2];
      #pragma unroll
      for (int mt=0;mt<2;mt++){
        int r = wm + mt*16 + g;
        af[mt][0] = __float_as_uint(Qs[r*FST + k + t4]);
        af[mt][1] = __float_as_uint(Qs[(r+8)*FST + k + t4]);
        af[mt][2] = __float_as_uint(Qs[r*FST + k + t4 + 4]);
        af[mt][3] = __float_as_uint(Qs[(r+8)*FST + k + t4 + 4]);
      }
      #pragma unroll
      for (int nt=0;nt<8;nt++){
        int n = wn + nt*8 + g;
        bf[nt][0] = __float_as_uint(Ks[n*FST + k + t4]);
        bf[nt][1] = __float_as_uint(Ks[n*FST + k + t4 + 4]);
      }
      #pragma unroll
      for (int mt=0;mt<2;mt++)
        #pragma unroll
        for (int nt=0;nt<8;nt++)
          mma8(s_acc[mt][nt], af[mt], bf[nt]);
    }

    const bool diag = (kt == qt);
    #pragma unroll
    for (int mt=0;mt<2;mt++)
      #pragma unroll
      for (int nt=0;nt<8;nt++)
        #pragma unroll
        for (int e=0;e<4;e++){
          int colL = wn + nt*8 + 2*t4 + (e & 1);
          int rowL = wm + mt*16 + g + ((e >> 1) << 3);
          float v = s_acc[mt][nt][e]*scale + km[colL];
          if (diag && colL > rowL) v = -1e30f;
          s_acc[mt][nt][e] = v;
        }

    #pragma unroll
    for (int ri=0;ri<4;ri++){
      int mt = ri>>1, hh = ri&1;
      float mx = -1e30f;
      #pragma unroll
      for (int nt=0;nt<8;nt++)
        mx = fmaxf(mx, fmaxf(s_acc[mt][nt][hh*2], s_acc[mt][nt][hh*2+1]));
      mx = fmaxf(mx, __shfl_xor_sync(0xffffffffu, mx, 1));
      mx = fmaxf(mx, __shfl_xor_sync(0xffffffffu, mx, 2));
      if (t4 == 0) redm[wnn*128 + wm + mt*16 + g + hh*8] = mx;
    }
    __syncthreads();

    float m_new[4], alpha[4], rsum[4];
    #pragma unroll
    for (int ri=0;ri<4;ri++){
      int rl = wm + (ri>>1)*16 + g + (ri&1)*8;
      float mtile = fmaxf(redm[rl], redm[128+rl]);
      m_new[ri] = fmaxf(m_prev[ri], mtile);
      alpha[ri] = __expf(m_prev[ri] - m_new[ri]);
      rsum[ri] = 0.f;
    }

    #pragma unroll
    for (int mt=0;mt<2;mt++)
      #pragma unroll
      for (int nt=0;nt<8;nt++)
        #pragma unroll
        for (int hh=0;hh<2;hh++){
          int ri = mt*2 + hh;
          float p0 = __expf(s_acc[mt][nt][hh*2]   - m_new[ri]);
          float p1 = __expf(s_acc[mt][nt][hh*2+1] - m_new[ri]);
          rsum[ri] += p0 + p1;
          int rowL = wm + mt*16 + g + hh*8;
          int colL = wn + nt*8 + 2*t4;
          float2 pv; pv.x = f2tff(p0); pv.y = f2tff(p1);
          *(float2*)&Ks[rowL*FST + colL] = pv;
          o_acc[mt][nt][hh*2]   *= alpha[ri];
          o_acc[mt][nt][hh*2+1] *= alpha[ri];
        }

    #pragma unroll
    for (int ri=0;ri<4;ri++){
      float s0 = rsum[ri];
      s0 += __shfl_xor_sync(0xffffffffu, s0, 1);
      s0 += __shfl_xor_sync(0xffffffffu, s0, 2);
      if (t4 == 0) reds[wnn*128 + wm + (ri>>1)*16 + g + (ri&1)*8] = s0;
    }
    __syncthreads();
    #pragma unroll
    for (int ri=0;ri<4;ri++){
      int rl = wm + (ri>>1)*16 + g + (ri&1)*8;
      l_run[ri] = l_run[ri]*alpha[ri] + reds[rl] + reds[128+rl];
      m_prev[ri] = m_new[ri];
    }

    #pragma unroll
    for (int ks=0; ks<16; ks++){
      const int k = ks*8;
      uint32_t af[2][4], bf[8][2];
      #pragma unroll
      for (int mt=0;mt<2;mt++){
        int r = wm + mt*16 + g;
        af[mt][0] = __float_as_uint(Ks[r*FST + k + t4]);
        af[mt][1] = __float_as_uint(Ks[(r+8)*FST + k + t4]);
        af[mt][2] = __float_as_uint(Ks[r*FST + k + t4 + 4]);
        af[mt][3] = __float_as_uint(Ks[(r+8)*FST + k + t4 + 4]);
      }
      #pragma unroll
      for (int nt=0;nt<8;nt++){
        int n = wn + nt*8 + g;
        bf[nt][0] = __float_as_uint(Vs[(k + t4)*FST + n]);
        bf[nt][1] = __float_as_uint(Vs[(k + t4 + 4)*FST + n]);
      }
      #pragma unroll
      for (int mt=0;mt<2;mt++)
        #pragma unroll
        for (int nt=0;nt<8;nt++)
          mma8(o_acc[mt][nt], af[mt], bf[nt]);
    }
  }

  // write O rounded to tf32 (A-operand of the final projection)
  float* Og = g_o + ((size_t)(b*SEQ + qt*128)) * EMB + headoff;
  #pragma unroll
  for (int mt=0;mt<2;mt++)
    #pragma unroll
    for (int hh=0;hh<2;hh++){
      int ri = mt*2 + hh;
      float inv = 1.0f / l_run[ri];
      int rowL = wm + mt*16 + g + hh*8;
      #pragma unroll
      for (int nt=0;nt<8;nt++){
        int colL = wn + nt*8 + 2*t4;
        float2 ov;
        ov.x = f2tff(o_acc[mt][nt][hh*2]   * inv);
        ov.y = f2tff(o_acc[mt][nt][hh*2+1] * inv);
        *(float2*)&Og[(size_t)rowL*EMB + colL] = ov;
      }
    }
}

// ---------------------------------------------------------------------------
extern "C" void kernel_launch(void* const* d_in, const int* in_sizes, int n_in,
                              void* d_out, int out_size){
  (void)in_sizes; (void)n_in; (void)out_size;
  const float* x  = (const float*)d_in[0];
  const float* wq = (const float*)d_in[1];
  const float* bq = (const float*)d_in[2];
  const float* wk = (const float*)d_in[3];
  const float* bk = (const float*)d_in[4];
  const float* wv = (const float*)d_in[5];
  const float* bv = (const float*)d_in[6];
  const float* wo = (const float*)d_in[7];
  const float* bo = (const float*)d_in[8];
  const unsigned char* amask = (const unsigned char*)d_in[10];
  float* out = (float*)d_out;

  cudaFuncSetAttribute(flash_kernel, cudaFuncAttributeMaxDynamicSharedMemorySize,
                       FLASH_SMEM_FLOATS * (int)sizeof(float));

  float *p_x, *p_wq, *p_wk, *p_wv, *p_wo;
  cudaGetSymbolAddress((void**)&p_x,  g_x);
  cudaGetSymbolAddress((void**)&p_wq, g_wq);
  cudaGetSymbolAddress((void**)&p_wk, g_wk);
  cudaGetSymbolAddress((void**)&p_wv, g_wv);
  cudaGetSymbolAddress((void**)&p_wo, g_wo);

  rope_tables_kernel<<<(SEQ*64 + 255)/256, 256>>>();

  const int nX4 = MTOT*EMB/4, nW4 = EMB*EMB/4;
  round_tf32_kernel<<<(nX4+255)/256, 256>>>(x,  p_x,  nX4);
  round_tf32_kernel<<<(nW4+255)/256, 256>>>(wq, p_wq, nW4);
  round_tf32_kernel<<<(nW4+255)/256, 256>>>(wk, p_wk, nW4);
  round_tf32_kernel<<<(nW4+255)/256, 256>>>(wv, p_wv, nW4);
  round_tf32_kernel<<<(nW4+255)/256, 256>>>(wo, p_wo, nW4);

  dim3 ggrid(EMB/128, MTOT/128);
  gemm_bias_kernel<<<ggrid, 256>>>(bq, nullptr, 0);
  gemm_bias_kernel<<<ggrid, 256>>>(bk, nullptr, 1);
  gemm_bias_kernel<<<ggrid, 256>>>(bv, nullptr, 2);

  rope_apply_kernel<<<(MTOT*NH*64 + 255)/256, 256>>>();

  flash_kernel<<<dim3(NB*NH, SEQ/128), 256, FLASH_SMEM_FLOATS*(int)sizeof(float)>>>(amask);

  gemm_bias_kernel<<<ggrid, 256>>>(bo, out, 3);
}